// round 8
// baseline (speedup 1.0000x reference)
#include <cuda_runtime.h>

#define Lc 2048
#define Bc 2048
#define NSEG 32
#define SEG 64           // owned steps per segment (2048/32)
#define WUP 8            // warmup steps (contraction ~0.1^8 ~ 1e-8)
#define PD 4             // steps per staged group / int prefetch depth
#define ROWF4 3584       // float4s per em step-row: 2048*7/4
#define GRPF4 (PD*ROWF4) // 14336

// ---------------- device scratch ----------------
__device__ float g_G [NSEG*Bc];
__device__ float g_sc[NSEG*Bc];
__device__ int   g_ct[NSEG*Bc];
__device__ float g_fin[Bc];
__device__ float g_part[16];

// ---------------- main segmented scan ----------------
// 512 blocks x 128 threads; s = blockIdx>>4, 16 blocks/segment, thread = (chain b, seg s).
__global__ __launch_bounds__(128) void crf_seg(
    const float* __restrict__ em,    const int* __restrict__ tags,
    const int*   __restrict__ qmask, const int* __restrict__ mask,
    const float* __restrict__ startT, const float* __restrict__ endT,
    const float* __restrict__ selfT,  const float* __restrict__ otherT)
{
    __shared__ float shS[49], shO[49], shEO[49];
    __shared__ float4 sEm4[4][224];          // per-warp: 4 steps x 224 floats
    for (int k = threadIdx.x; k < 49; k += 128) {
        float o = otherT[k];
        shS[k] = selfT[k]; shO[k] = o; shEO[k] = __expf(o);
    }
    __syncthreads();

    const int wid  = threadIdx.x >> 5, lane = threadIdx.x & 31;
    const int s    = blockIdx.x >> 4;
    const int b    = ((blockIdx.x & 15) << 7) + threadIdx.x;
    const int b0   = ((blockIdx.x & 15) << 7) + (wid << 5);   // warp's base chain
    const bool safe = (s != NSEG - 1);       // only seg 31 can touch l > Lc-1
    float4* sd = sEm4[wid];
    const float* sE = (const float*)sd;
    const int sOfs = 7 * lane;               // this thread's float offset in a step row

    // exp(self) matrix in registers (uniform broadcast loads)
    float Es[49];
#pragma unroll
    for (int k = 0; k < 49; k++) Es[k] = __expf(selfT[k]);

    float w[7], C, score;
    int cnt, qprev, tgprev, lstart, ngrp;

    if (s == 0) {
        lstart = 1; ngrp = SEG / PD;                        // steps l = 1..64
        const float* e0 = em + (size_t)b * 7;
        float a[7]; float m = -1e30f;
#pragma unroll
        for (int j = 0; j < 7; j++) { a[j] = startT[j] + e0[j]; m = fmaxf(m, a[j]); }
#pragma unroll
        for (int j = 0; j < 7; j++) w[j] = __expf(a[j] - m);
        C = m;
        const int tg0 = tags[b];
        float et = e0[0];
#pragma unroll
        for (int j = 1; j < 7; j++) et = (tg0 == j) ? e0[j] : et;
        score = startT[tg0] + et;
        cnt = mask[b];
        qprev = qmask[b]; tgprev = tg0;
    } else {
        lstart = s * SEG - WUP + 1; ngrp = (SEG + WUP) / PD;  // 72 steps
#pragma unroll
        for (int j = 0; j < 7; j++) w[j] = 1.0f;
        C = 0.f; score = 0.f; cnt = 0;
        const int pb = (lstart - 1) * Bc + b;
        qprev = qmask[pb]; tgprev = tags[pb];
    }
    const int resetg = (s == 0) ? -1 : (WUP / PD - 1);   // after step l = s*SEG

    // ---- em group pointer + prologue load of group 0 (rows always in-bounds) ----
    const float4* gp = (const float4*)(em + ((size_t)lstart * Bc + b0) * 7);
    float4 A0, A1, A2, A3, B0, B1, B2, B3;
    {
        const float4* q = gp;
        A0 = q[lane];            A1 = q[ROWF4 + lane];
        A2 = q[2*ROWF4 + lane];  A3 = q[3*ROWF4 + lane];
        if (lane < 24) {
            B0 = q[32 + lane];           B1 = q[ROWF4 + 32 + lane];
            B2 = q[2*ROWF4 + 32 + lane]; B3 = q[3*ROWF4 + 32 + lane];
        }
    }

    // ---- int prefetch ring ----
    int mkb[PD], qb[PD], tgb[PD];
#pragma unroll
    for (int k = 0; k < PD; k++) {
        const int bb = (lstart + k) * Bc + b;
        mkb[k] = mask[bb]; qb[k] = qmask[bb]; tgb[k] = tags[bb];
    }

#pragma unroll 1
    for (int g = 0; g < ngrp; g++) {
        __syncwarp();                     // WAR: prior group's LDS done
        sd[lane]       = A0; sd[56  + lane] = A1;
        sd[112 + lane] = A2; sd[168 + lane] = A3;
        if (lane < 24) {
            sd[32  + lane] = B0; sd[88  + lane] = B1;
            sd[144 + lane] = B2; sd[200 + lane] = B3;
        }
        __syncwarp();                     // RAW: STS visible to warp

        // prefetch em for group g+1 (used 4..8 steps later)
        if (g + 1 < ngrp) {
            const int lnext = lstart + (g + 1) * PD;
            if (lnext + PD - 1 <= Lc - 1) {
                const float4* q = gp + (size_t)(g + 1) * GRPF4;
                A0 = q[lane];            A1 = q[ROWF4 + lane];
                A2 = q[2*ROWF4 + lane];  A3 = q[3*ROWF4 + lane];
                if (lane < 24) {
                    B0 = q[32 + lane];           B1 = q[ROWF4 + 32 + lane];
                    B2 = q[2*ROWF4 + 32 + lane]; B3 = q[3*ROWF4 + 32 + lane];
                }
            } else {                       // only seg 31's final prefetch
                const float4* q0 = (const float4*)(em + ((size_t)min(lnext    , Lc-1) * Bc + b0) * 7);
                const float4* q1 = (const float4*)(em + ((size_t)min(lnext + 1, Lc-1) * Bc + b0) * 7);
                const float4* q2 = (const float4*)(em + ((size_t)min(lnext + 2, Lc-1) * Bc + b0) * 7);
                const float4* q3 = (const float4*)(em + ((size_t)min(lnext + 3, Lc-1) * Bc + b0) * 7);
                A0 = q0[lane]; A1 = q1[lane]; A2 = q2[lane]; A3 = q3[lane];
                if (lane < 24) { B0 = q0[32+lane]; B1 = q1[32+lane]; B2 = q2[32+lane]; B3 = q3[32+lane]; }
            }
        }

        // ---- process 4 steps from smem ----
#pragma unroll
        for (int k = 0; k < PD; k++) {
            const int mk = mkb[k], q = qb[k], tg = tgb[k];
            const bool cont = (q != qprev);

            // int prefetch for step g*PD + k + PD
            if (safe) {                    // uniform branch; no clamp math
                const int bb = (lstart + g * PD + k + PD) * Bc + b;
                mkb[k] = mask[bb]; qb[k] = qmask[bb]; tgb[k] = tags[bb];
            } else {                       // seg 31 tail: clamp, OOB => mk=0
                int lp = lstart + g * PD + k + PD;
                const int oob = (lp > Lc - 1);
                lp = oob ? (Lc - 1) : lp;
                const int bb = lp * Bc + b;
                mkb[k] = oob ? 0 : mask[bb];
                qb[k] = qmask[bb]; tgb[k] = tags[bb];
            }

            float x[7], e[7];
#pragma unroll
            for (int j = 0; j < 7; j++) x[j] = sE[k * 224 + sOfs + j];
#pragma unroll
            for (int j = 0; j < 7; j++) e[j] = __expf(x[j]);

            float sv[7];
            if (!cont) {
#pragma unroll
                for (int j = 0; j < 7; j++) sv[j] = w[0] * Es[j];
#pragma unroll
                for (int i = 1; i < 7; i++)
#pragma unroll
                    for (int j = 0; j < 7; j++) sv[j] = fmaf(w[i], Es[i * 7 + j], sv[j]);
            } else {
#pragma unroll
                for (int j = 0; j < 7; j++) sv[j] = w[0] * shEO[j];
#pragma unroll
                for (int i = 1; i < 7; i++)
#pragma unroll
                    for (int j = 0; j < 7; j++) sv[j] = fmaf(w[i], shEO[i * 7 + j], sv[j]);
            }

            if (mk) {
#pragma unroll
                for (int j = 0; j < 7; j++) w[j] = sv[j] * e[j];
                const float et = sE[k * 224 + sOfs + tg];     // dynamic LDS, no sel chain
                score += et + (cont ? shO : shS)[tgprev * 7 + tg];
                qprev = q; tgprev = tg;
            }
            cnt += mk;
        }

        if (g == resetg) {
            // warmup -> owned boundary: normalize direction, zero accumulators
            float m = w[0];
#pragma unroll
            for (int j = 1; j < 7; j++) m = fmaxf(m, w[j]);
            const float inv = 1.f / m;
#pragma unroll
            for (int j = 0; j < 7; j++) w[j] *= inv;
            C = 0.f; score = 0.f; cnt = 0;
        } else if (g & 1) {
            // renormalize every 8 steps
            float m = w[0];
#pragma unroll
            for (int j = 1; j < 7; j++) m = fmaxf(m, w[j]);
            C += __logf(m);
            const float inv = 1.f / m;
#pragma unroll
            for (int j = 0; j < 7; j++) w[j] *= inv;
        }
    }

    // finalize segment
    float m = w[0];
#pragma unroll
    for (int j = 1; j < 7; j++) m = fmaxf(m, w[j]);
    g_G [s * Bc + b] = C + __logf(m);
    g_sc[s * Bc + b] = score;
    g_ct[s * Bc + b] = cnt;
    if (s == NSEG - 1) {
        const float inv = 1.f / m;
        float sum = 0.f;
#pragma unroll
        for (int j = 0; j < 7; j++) sum += w[j] * inv * __expf(endT[j]);
        g_fin[b] = __logf(sum);
    }
}

// ---------------- per-chain combine + partial sums ----------------
__global__ void crf_fin(const int* __restrict__ tags,
                        const float* __restrict__ endT) {
    const int b = blockIdx.x * blockDim.x + threadIdx.x;   // 16 x 128 = 2048
    float G = 0.f, sc = 0.f; int ct = 0;
#pragma unroll
    for (int s = 0; s < NSEG; s++) {
        G  += g_G [s * Bc + b];
        sc += g_sc[s * Bc + b];
        ct += g_ct[s * Bc + b];
    }
    const float logZ = G + g_fin[b];
    const int tg_end = tags[(size_t)(ct - 1) * Bc + b];
    const float llh = sc + endT[tg_end] - logZ;

    __shared__ float red[128];
    red[threadIdx.x] = llh;
    __syncthreads();
    for (int off = 64; off > 0; off >>= 1) {
        if (threadIdx.x < off) red[threadIdx.x] += red[threadIdx.x + off];
        __syncthreads();
    }
    if (threadIdx.x == 0) g_part[blockIdx.x] = red[0];
}

__global__ void crf_fin2(float* __restrict__ out) {
    if (threadIdx.x == 0) {
        float s = 0.f;
        for (int k = 0; k < 16; k++) s += g_part[k];
        out[0] = s;
    }
}

// ---------------- launch ----------------
extern "C" void kernel_launch(void* const* d_in, const int* in_sizes, int n_in,
                              void* d_out, int out_size) {
    const float* em     = (const float*)d_in[0];
    const int*   tags   = (const int*)  d_in[1];
    const int*   qmask  = (const int*)  d_in[2];
    const int*   mask   = (const int*)  d_in[3];
    const float* startT = (const float*)d_in[4];
    const float* endT   = (const float*)d_in[5];
    const float* selfT  = (const float*)d_in[6];
    const float* otherT = (const float*)d_in[7];
    float* out = (float*)d_out;

    crf_seg<<<NSEG * 16, 128>>>(em, tags, qmask, mask, startT, endT, selfT, otherT);
    crf_fin<<<16, 128>>>(tags, endT);
    crf_fin2<<<1, 32>>>(out);
}

// round 10
// speedup vs baseline: 1.1193x; 1.1193x over previous
#include <cuda_runtime.h>

#define Lc 2048
#define Bc 2048
#define NSEG 37          // grid = 37*16 = 592 = 4 blocks x 148 SMs, single balanced wave
#define WUP 8            // warmup steps (contraction ~0.1^8 ~ 1e-8)
#define PD 4             // steps per staged group / int prefetch depth
#define NBUF 3           // smem ring buffers (prefetch distance 2 groups)

typedef unsigned int u32;

// ---------------- device scratch ----------------
__device__ float g_G [NSEG*Bc];
__device__ float g_sc[NSEG*Bc];
__device__ int   g_ct[NSEG*Bc];
__device__ float g_fin[Bc];
__device__ float g_part[16];

__device__ __forceinline__ void cp16(u32 dst, const void* src) {
    asm volatile("cp.async.cg.shared.global [%0], [%1], 16;" :: "r"(dst), "l"(src));
}
__device__ __forceinline__ void cp_commit() { asm volatile("cp.async.commit_group;"); }
__device__ __forceinline__ void cp_wait2()  { asm volatile("cp.async.wait_group 2;"); }

// ---------------- main segmented scan ----------------
// 592 blocks x 128 threads; s = blockIdx>>4, 16 blocks/segment, thread = (chain b, seg s).
__global__ __launch_bounds__(128, 4) void crf_seg(
    const float* __restrict__ em,    const int* __restrict__ tags,
    const int*   __restrict__ qmask, const int* __restrict__ mask,
    const float* __restrict__ startT, const float* __restrict__ endT,
    const float* __restrict__ selfT,  const float* __restrict__ otherT)
{
    __shared__ float shS[49], shO[49], shEO[49];
    __shared__ float4 sEm4[4][NBUF*224];     // per-warp ring: 3 bufs x (4 steps x 224 floats)
    for (int k = threadIdx.x; k < 49; k += 128) {
        float o = otherT[k];
        shS[k] = selfT[k]; shO[k] = o; shEO[k] = __expf(o);
    }
    __syncthreads();

    const int wid  = threadIdx.x >> 5, lane = threadIdx.x & 31;
    const int s    = blockIdx.x >> 4;
    const int b    = ((blockIdx.x & 15) << 7) + threadIdx.x;
    const int b0   = ((blockIdx.x & 15) << 7) + (wid << 5);   // warp's base chain
    float4* sd = sEm4[wid];
    const float* sEbase = (const float*)sd;
    const int sOfs = 7 * lane;
    // cp.async mapping: thread covers row r = lane>>3, chunk c = lane&7 (7 float4s)
    const int cprow = lane >> 3, cpc = (lane & 7) * 7;
    u32 sdAddr = (u32)__cvta_generic_to_shared(sd);

    // exp(self) matrix in registers (uniform broadcast loads)
    float Es[49];
#pragma unroll
    for (int k = 0; k < 49; k++) Es[k] = __expf(selfT[k]);

    // segment bounds: owned transitions l in (startl, lend]
    const int startl = (s * Lc) / NSEG;
    const int lend0  = ((s + 1) * Lc) / NSEG;
    const int lend   = (lend0 > Lc - 1) ? (Lc - 1) : lend0;   // only s=36 clamps

    float w[7], C, score;
    int cnt, qprev, tgprev, lstart, ngrp;

    if (s == 0) {
        lstart = 1; ngrp = (lend0 + PD - 1) / PD;             // 14 groups, 55 real steps
        const float* e0 = em + (size_t)b * 7;
        float a[7]; float m = -1e30f;
#pragma unroll
        for (int j = 0; j < 7; j++) { a[j] = startT[j] + e0[j]; m = fmaxf(m, a[j]); }
#pragma unroll
        for (int j = 0; j < 7; j++) w[j] = __expf(a[j] - m);
        C = m;
        const int tg0 = tags[b];
        float et = e0[0];
#pragma unroll
        for (int j = 1; j < 7; j++) et = (tg0 == j) ? e0[j] : et;
        score = startT[tg0] + et;
        cnt = mask[b];
        qprev = qmask[b]; tgprev = tg0;
    } else {
        lstart = startl - WUP + 1;
        ngrp = (lend0 - lstart + 1 + PD - 1) / PD;            // 16 groups (63-64 steps)
#pragma unroll
        for (int j = 0; j < 7; j++) w[j] = 1.0f;
        C = 0.f; score = 0.f; cnt = 0;
        const int pb = (lstart - 1) * Bc + b;
        qprev = qmask[pb]; tgprev = tags[pb];
    }
    const int resetg = (s == 0) ? -1 : (WUP / PD - 1);        // reset after step l = startl

    // ---- cp.async prologue: groups 0 and 1 into slots 0,1 ----
#pragma unroll
    for (int pg = 0; pg < 2; pg++) {
        int l = lstart + pg * PD + cprow; l = (l > Lc - 1) ? (Lc - 1) : l;
        const float4* src = (const float4*)(em + ((size_t)l * Bc + b0) * 7) + cpc;
        u32 dst = sdAddr + (u32)(pg * 224 + cprow * 56 + cpc) * 16u;
#pragma unroll
        for (int i = 0; i < 7; i++) cp16(dst + i * 16u, src + i);
        cp_commit();
    }

    // ---- int prefetch ring (gated at load time) ----
    int mkb[PD], qb[PD], tgb[PD];
#pragma unroll
    for (int k = 0; k < PD; k++) {
        const int lp = lstart + k;
        const int bb = lp * Bc + b;                            // always <= 2047 here
        mkb[k] = (lp <= lend) ? mask[bb] : 0;
        qb[k] = qmask[bb]; tgb[k] = tags[bb];
    }

    int slot = 0;                                              // slot of current group
#pragma unroll 1
    for (int g = 0; g < ngrp; g++) {
        // issue cp.async for group g+2 into slot (g+2)%3
        if (g + 2 < ngrp) {
            const int slot2 = (slot + 2 >= NBUF) ? (slot + 2 - NBUF) : (slot + 2);
            const int lb = lstart + (g + 2) * PD + cprow;
            const int l = (lb > Lc - 1) ? (Lc - 1) : lb;
            const float4* src = (const float4*)(em + ((size_t)l * Bc + b0) * 7) + cpc;
            u32 dst = sdAddr + (u32)(slot2 * 224 + cprow * 56 + cpc) * 16u;
#pragma unroll
            for (int i = 0; i < 7; i++) cp16(dst + i * 16u, src + i);
        }
        cp_commit();
        cp_wait2();                     // group g complete (<=2 groups in flight)
        __syncwarp();

        const float* sE = sEbase + slot * 896;

        // ---- process 4 steps from smem ----
#pragma unroll
        for (int k = 0; k < PD; k++) {
            const int mk = mkb[k], q = qb[k], tg = tgb[k];
            const bool cont = (q != qprev);

            // int prefetch for step g*PD + k + PD (gated, clamped)
            {
                const int lp = lstart + g * PD + k + PD;
                const int lpc = (lp > Lc - 1) ? (Lc - 1) : lp;
                const int bb = lpc * Bc + b;
                mkb[k] = (lp <= lend) ? mask[bb] : 0;
                qb[k] = qmask[bb]; tgb[k] = tags[bb];
            }

            float x[7], e[7];
#pragma unroll
            for (int j = 0; j < 7; j++) x[j] = sE[k * 224 + sOfs + j];
#pragma unroll
            for (int j = 0; j < 7; j++) e[j] = __expf(x[j]);

            float sv[7];
            if (!cont) {
#pragma unroll
                for (int j = 0; j < 7; j++) sv[j] = w[0] * Es[j];
#pragma unroll
                for (int i = 1; i < 7; i++)
#pragma unroll
                    for (int j = 0; j < 7; j++) sv[j] = fmaf(w[i], Es[i * 7 + j], sv[j]);
            } else {
#pragma unroll
                for (int j = 0; j < 7; j++) sv[j] = w[0] * shEO[j];
#pragma unroll
                for (int i = 1; i < 7; i++)
#pragma unroll
                    for (int j = 0; j < 7; j++) sv[j] = fmaf(w[i], shEO[i * 7 + j], sv[j]);
            }

            if (mk) {
#pragma unroll
                for (int j = 0; j < 7; j++) w[j] = sv[j] * e[j];
                const float et = sE[k * 224 + sOfs + tg];      // dynamic LDS
                score += et + (cont ? shO : shS)[tgprev * 7 + tg];
                qprev = q; tgprev = tg;
            }
            cnt += mk;
        }
        __syncwarp();                   // all lanes done reading slot before reuse

        if (g == resetg) {
            // warmup -> owned boundary: normalize direction, zero accumulators
            float m = w[0];
#pragma unroll
            for (int j = 1; j < 7; j++) m = fmaxf(m, w[j]);
            const float inv = 1.f / m;
#pragma unroll
            for (int j = 0; j < 7; j++) w[j] *= inv;
            C = 0.f; score = 0.f; cnt = 0;
        } else if (g & 1) {
            // renormalize every 8 steps
            float m = w[0];
#pragma unroll
            for (int j = 1; j < 7; j++) m = fmaxf(m, w[j]);
            C += __logf(m);
            const float inv = 1.f / m;
#pragma unroll
            for (int j = 0; j < 7; j++) w[j] *= inv;
        }

        slot = (slot + 1 >= NBUF) ? 0 : (slot + 1);
    }

    // finalize segment
    float m = w[0];
#pragma unroll
    for (int j = 1; j < 7; j++) m = fmaxf(m, w[j]);
    g_G [s * Bc + b] = C + __logf(m);
    g_sc[s * Bc + b] = score;
    g_ct[s * Bc + b] = cnt;
    if (s == NSEG - 1) {
        const float inv = 1.f / m;
        float sum = 0.f;
#pragma unroll
        for (int j = 0; j < 7; j++) sum += w[j] * inv * __expf(endT[j]);
        g_fin[b] = __logf(sum);
    }
}

// ---------------- per-chain combine + partial sums ----------------
__global__ void crf_fin(const int* __restrict__ tags,
                        const float* __restrict__ endT) {
    const int b = blockIdx.x * blockDim.x + threadIdx.x;   // 16 x 128 = 2048
    float G = 0.f, sc = 0.f; int ct = 0;
#pragma unroll
    for (int s = 0; s < NSEG; s++) {
        G  += g_G [s * Bc + b];
        sc += g_sc[s * Bc + b];
        ct += g_ct[s * Bc + b];
    }
    const float logZ = G + g_fin[b];
    const int tg_end = tags[(size_t)(ct - 1) * Bc + b];
    const float llh = sc + endT[tg_end] - logZ;

    __shared__ float red[128];
    red[threadIdx.x] = llh;
    __syncthreads();
    for (int off = 64; off > 0; off >>= 1) {
        if (threadIdx.x < off) red[threadIdx.x] += red[threadIdx.x + off];
        __syncthreads();
    }
    if (threadIdx.x == 0) g_part[blockIdx.x] = red[0];
}

__global__ void crf_fin2(float* __restrict__ out) {
    if (threadIdx.x == 0) {
        float s = 0.f;
        for (int k = 0; k < 16; k++) s += g_part[k];
        out[0] = s;
    }
}

// ---------------- launch ----------------
extern "C" void kernel_launch(void* const* d_in, const int* in_sizes, int n_in,
                              void* d_out, int out_size) {
    const float* em     = (const float*)d_in[0];
    const int*   tags   = (const int*)  d_in[1];
    const int*   qmask  = (const int*)  d_in[2];
    const int*   mask   = (const int*)  d_in[3];
    const float* startT = (const float*)d_in[4];
    const float* endT   = (const float*)d_in[5];
    const float* selfT  = (const float*)d_in[6];
    const float* otherT = (const float*)d_in[7];
    float* out = (float*)d_out;

    crf_seg<<<NSEG * 16, 128>>>(em, tags, qmask, mask, startT, endT, selfT, otherT);
    crf_fin<<<16, 128>>>(tags, endT);
    crf_fin2<<<1, 32>>>(out);
}